// round 1
// baseline (speedup 1.0000x reference)
#include <cuda_runtime.h>

// Sigma = Q diag(exp(2*log_s)) Q^T, Q from normalized quaternion.
// Normalization folded into rotmat via inv = 2/|q|^2 (R entries bilinear in q).

__global__ __launch_bounds__(256)
void gaussian_cov_kernel(const float4* __restrict__ q,
                         const float*  __restrict__ ls,
                         float* __restrict__ out,
                         int n)
{
    int i = blockIdx.x * blockDim.x + threadIdx.x;
    if (i >= n) return;

    float4 qv = q[i];
    float w = qv.x, x = qv.y, y = qv.z, z = qv.w;

    float n2  = fmaf(w, w, fmaf(x, x, fmaf(y, y, z * z)));
    float inv = __fdividef(2.0f, n2);

    float xx = x * x, yy = y * y, zz = z * z;
    float xy = x * y, xz = x * z, yz = y * z;
    float wx = w * x, wy = w * y, wz = w * z;

    float r00 = 1.0f - inv * (yy + zz);
    float r01 = inv * (xy - wz);
    float r02 = inv * (xz + wy);
    float r10 = inv * (xy + wz);
    float r11 = 1.0f - inv * (xx + zz);
    float r12 = inv * (yz - wx);
    float r20 = inv * (xz - wy);
    float r21 = inv * (yz + wx);
    float r22 = 1.0f - inv * (xx + yy);

    float s0 = __expf(2.0f * ls[3 * i + 0]);
    float s1 = __expf(2.0f * ls[3 * i + 1]);
    float s2 = __expf(2.0f * ls[3 * i + 2]);

    // weighted rows: a_j = s_j * r0j etc.
    float a0 = s0 * r00, a1 = s1 * r01, a2 = s2 * r02;
    float b0 = s0 * r10, b1 = s1 * r11, b2 = s2 * r12;
    float c0 = s0 * r20, c1 = s1 * r21, c2 = s2 * r22;

    float s00 = fmaf(a0, r00, fmaf(a1, r01, a2 * r02));
    float s01 = fmaf(a0, r10, fmaf(a1, r11, a2 * r12));
    float s02 = fmaf(a0, r20, fmaf(a1, r21, a2 * r22));
    float s11 = fmaf(b0, r10, fmaf(b1, r11, b2 * r12));
    float s12 = fmaf(b0, r20, fmaf(b1, r21, b2 * r22));
    float s22 = fmaf(c0, r20, fmaf(c1, r21, c2 * r22));

    float* o = out + (size_t)9 * i;
    o[0] = s00; o[1] = s01; o[2] = s02;
    o[3] = s01; o[4] = s11; o[5] = s12;
    o[6] = s02; o[7] = s12; o[8] = s22;
}

extern "C" void kernel_launch(void* const* d_in, const int* in_sizes, int n_in,
                              void* d_out, int out_size)
{
    const float4* q  = (const float4*)d_in[0];   // (N,4) float32
    const float*  ls = (const float*)d_in[1];    // (N,3) float32
    float* out = (float*)d_out;                  // (N,3,3) float32
    int n = in_sizes[0] / 4;

    int block = 256;
    int grid = (n + block - 1) / block;
    gaussian_cov_kernel<<<grid, block>>>(q, ls, out, n);
}

// round 2
// speedup vs baseline: 2.8397x; 2.8397x over previous
#include <cuda_runtime.h>

// Sigma = Q diag(exp(2*log_s)) Q^T, normalization folded in (inv = 2/|q|^2).
// Smem-staged I/O: coalesced float4 loads for log_s and float4 stores for Sigma.

#define BLK 256

__device__ __forceinline__ void compute_sigma(float w, float x, float y, float z,
                                              float s0, float s1, float s2,
                                              float* r /*6 outs*/)
{
    float n2  = fmaf(w, w, fmaf(x, x, fmaf(y, y, z * z)));
    float inv = __fdividef(2.0f, n2);

    float xx = x * x, yy = y * y, zz = z * z;
    float xy = x * y, xz = x * z, yz = y * z;
    float wx = w * x, wy = w * y, wz = w * z;

    float r00 = 1.0f - inv * (yy + zz);
    float r01 = inv * (xy - wz);
    float r02 = inv * (xz + wy);
    float r10 = inv * (xy + wz);
    float r11 = 1.0f - inv * (xx + zz);
    float r12 = inv * (yz - wx);
    float r20 = inv * (xz - wy);
    float r21 = inv * (yz + wx);
    float r22 = 1.0f - inv * (xx + yy);

    float a0 = s0 * r00, a1 = s1 * r01, a2 = s2 * r02;
    float b0 = s0 * r10, b1 = s1 * r11, b2 = s2 * r12;
    float c0 = s0 * r20, c1 = s1 * r21, c2 = s2 * r22;

    r[0] = fmaf(a0, r00, fmaf(a1, r01, a2 * r02)); // s00
    r[1] = fmaf(a0, r10, fmaf(a1, r11, a2 * r12)); // s01
    r[2] = fmaf(a0, r20, fmaf(a1, r21, a2 * r22)); // s02
    r[3] = fmaf(b0, r10, fmaf(b1, r11, b2 * r12)); // s11
    r[4] = fmaf(b0, r20, fmaf(b1, r21, b2 * r22)); // s12
    r[5] = fmaf(c0, r20, fmaf(c1, r21, c2 * r22)); // s22
}

__global__ __launch_bounds__(BLK)
void gaussian_cov_kernel(const float4* __restrict__ q,
                         const float*  __restrict__ ls,
                         float* __restrict__ out,
                         int n)
{
    __shared__ float s_ls[BLK * 3];       // 3072 B
    __shared__ float s_out[BLK * 9];      // 9216 B

    int tid  = threadIdx.x;
    int base = blockIdx.x * BLK;
    int valid = n - base;

    if (valid >= BLK) {
        // ---- fast path: full block, fully vectorized I/O ----
        // stage log_s: 256*3 floats = 192 float4, coalesced
        const float4* lsv = (const float4*)(ls + (size_t)base * 3);
        if (tid < 192) ((float4*)s_ls)[tid] = lsv[tid];
        __syncthreads();

        float4 qv = q[base + tid];
        float s0 = __expf(2.0f * s_ls[tid * 3 + 0]);
        float s1 = __expf(2.0f * s_ls[tid * 3 + 1]);
        float s2 = __expf(2.0f * s_ls[tid * 3 + 2]);

        float r[6];
        compute_sigma(qv.x, qv.y, qv.z, qv.w, s0, s1, s2, r);

        // stride-9 STS: gcd(9,32)=1 -> conflict-free
        float* so = s_out + tid * 9;
        so[0] = r[0]; so[1] = r[1]; so[2] = r[2];
        so[3] = r[1]; so[4] = r[3]; so[5] = r[4];
        so[6] = r[2]; so[7] = r[4]; so[8] = r[5];
        __syncthreads();

        // stream out: 256*9 floats = 576 float4, coalesced
        float4* ov = (float4*)(out + (size_t)base * 9);
        const float4* sv = (const float4*)s_out;
        #pragma unroll
        for (int t = tid; t < 576; t += BLK) ov[t] = sv[t];
    } else {
        // ---- tail path: scalar (N=4M is divisible by 256, so normally unused) ----
        int i = base + tid;
        if (i >= n) return;
        float4 qv = q[i];
        float s0 = __expf(2.0f * ls[3 * i + 0]);
        float s1 = __expf(2.0f * ls[3 * i + 1]);
        float s2 = __expf(2.0f * ls[3 * i + 2]);
        float r[6];
        compute_sigma(qv.x, qv.y, qv.z, qv.w, s0, s1, s2, r);
        float* o = out + (size_t)9 * i;
        o[0] = r[0]; o[1] = r[1]; o[2] = r[2];
        o[3] = r[1]; o[4] = r[3]; o[5] = r[4];
        o[6] = r[2]; o[7] = r[4]; o[8] = r[5];
    }
}

extern "C" void kernel_launch(void* const* d_in, const int* in_sizes, int n_in,
                              void* d_out, int out_size)
{
    const float4* q  = (const float4*)d_in[0];   // (N,4) float32
    const float*  ls = (const float*)d_in[1];    // (N,3) float32
    float* out = (float*)d_out;                  // (N,3,3) float32
    int n = in_sizes[0] / 4;

    int grid = (n + BLK - 1) / BLK;
    gaussian_cov_kernel<<<grid, BLK>>>(q, ls, out, n);
}